// round 3
// baseline (speedup 1.0000x reference)
#include <cuda_runtime.h>
#include <cstdint>

#define D 64
#define H 128
#define NMAX 50048

// Scratch tables: P[n][128], Q[n][128] (node-factored layer-1 preactivations)
__device__ __align__(16) float g_P[(size_t)NMAX * H];
__device__ __align__(16) float g_Q[(size_t)NMAX * H];

typedef unsigned long long ull;

__device__ __forceinline__ void fma2(ull& acc, ull a, ull b) {
    asm("fma.rn.f32x2 %0, %1, %2, %0;" : "+l"(acc) : "l"(a), "l"(b));
}
__device__ __forceinline__ ull pack2(float x, float y) {
    ull r; asm("mov.b64 %0, {%1, %2};" : "=l"(r) : "f"(x), "f"(y)); return r;
}
__device__ __forceinline__ float2 unpack2(ull v) {
    float2 r; asm("mov.b64 {%0, %1}, %2;" : "=f"(r.x), "=f"(r.y) : "l"(v)); return r;
}
__device__ __forceinline__ float sigmoidf_(float x) {
    return __fdividef(1.0f, 1.0f + __expf(-x));
}

// ---------------------------------------------------------------------------
// Kernel 1: per-node precompute
//   P[n][i] = b1[i] + W1a[i,:]*h1[n] + (W1c+W1d)[i,:]*h2[n]
//   Q[n][i] =          W1b[i,:]*h1[n]
// Block: 128 threads (thread = output i), 128 nodes/block in groups of 8.
// Weights staged transposed in smem with stride 129 (conflict-free both ways).
// ---------------------------------------------------------------------------
#define PRE_SMEM_FLOATS (3 * 64 * 129 + 2 * 512)
#define PRE_SMEM_BYTES (PRE_SMEM_FLOATS * 4)

__global__ void __launch_bounds__(128) precompute_kernel(
    const float* __restrict__ h1, const float* __restrict__ h2,
    const float* __restrict__ W1, const float* __restrict__ b1, int n)
{
    extern __shared__ float sm[];
    float* WaT = sm;                 // [k][i], stride 129
    float* WbT = sm + 64 * 129;
    float* WcT = sm + 2 * 64 * 129;
    float* hs1 = sm + 3 * 64 * 129;  // [k][8]
    float* hs2 = hs1 + 512;

    const int t = threadIdx.x;

    // Stage weights: coalesced global reads (k fast), conflict-free STS (stride 129)
    for (int idx = t; idx < 64 * 128; idx += 128) {
        int k = idx & 63, i = idx >> 6;
        WaT[k * 129 + i] = W1[i * 256 + k];
        WbT[k * 129 + i] = W1[i * 256 + 64 + k];
        WcT[k * 129 + i] = W1[i * 256 + 128 + k] + W1[i * 256 + 192 + k];
    }
    const float b1i = b1[t];
    __syncthreads();

    const int n0b = blockIdx.x * 128;
    for (int g = 0; g < 16; ++g) {
        const int n0 = n0b + g * 8;
        // Stage 8 nodes' features (coalesced over k)
        #pragma unroll
        for (int r = 0; r < 4; ++r) {
            int idx = r * 128 + t;
            int k = idx & 63, nn = idx >> 6;
            int node = n0 + nn;
            float v1 = 0.f, v2 = 0.f;
            if (node < n) { v1 = h1[node * D + k]; v2 = h2[node * D + k]; }
            hs1[k * 8 + nn] = v1;
            hs2[k * 8 + nn] = v2;
        }
        __syncthreads();

        ull accP[4] = {0, 0, 0, 0}, accQ[4] = {0, 0, 0, 0};
        #pragma unroll 8
        for (int k = 0; k < 64; ++k) {
            float wa = WaT[k * 129 + t];
            float wb = WbT[k * 129 + t];
            float wc = WcT[k * 129 + t];
            ull wa2 = pack2(wa, wa), wb2 = pack2(wb, wb), wc2 = pack2(wc, wc);
            const ulonglong2* p1 = (const ulonglong2*)(hs1 + k * 8);  // broadcast
            const ulonglong2* p2 = (const ulonglong2*)(hs2 + k * 8);
            ulonglong2 x1a = p1[0], x1b = p1[1];
            ulonglong2 x2a = p2[0], x2b = p2[1];
            fma2(accP[0], wa2, x1a.x); fma2(accP[1], wa2, x1a.y);
            fma2(accP[2], wa2, x1b.x); fma2(accP[3], wa2, x1b.y);
            fma2(accP[0], wc2, x2a.x); fma2(accP[1], wc2, x2a.y);
            fma2(accP[2], wc2, x2b.x); fma2(accP[3], wc2, x2b.y);
            fma2(accQ[0], wb2, x1a.x); fma2(accQ[1], wb2, x1a.y);
            fma2(accQ[2], wb2, x1b.x); fma2(accQ[3], wb2, x1b.y);
        }
        #pragma unroll
        for (int p = 0; p < 4; ++p) {
            float2 vp = unpack2(accP[p]);
            float2 vq = unpack2(accQ[p]);
            int na = n0 + 2 * p, nb = na + 1;
            if (na < n) { g_P[(size_t)na * H + t] = vp.x + b1i; g_Q[(size_t)na * H + t] = vq.x; }
            if (nb < n) { g_P[(size_t)nb * H + t] = vp.y + b1i; g_Q[(size_t)nb * H + t] = vq.y; }
        }
        __syncthreads();
    }
}

// ---------------------------------------------------------------------------
// Kernel 2: per-edge
//   z1 = sigmoid(P[src] + Q[dst]); z2 = sigmoid(W2 z1 + b2); out = W3.z2 + b3
// Block: 128 threads, tile = 32 edges. Warp w handles edges 8w..8w+7, all 128
// outputs (4 per lane). W2 transposed in smem stride 132 (aligned LDS.128);
// z1 staged as duplicated (z,z) pairs so f32x2 operands need no pack movs.
// Indices are int32 (JAX x64-disabled downcasts the int64 request).
// ---------------------------------------------------------------------------
#define EDGE_SMEM_FLOATS (128 * 132 + 128 * 64)
#define EDGE_SMEM_BYTES (EDGE_SMEM_FLOATS * 4)

__global__ void __launch_bounds__(128) edge_kernel(
    const int* __restrict__ src, const int* __restrict__ dst,
    const float* __restrict__ W2, const float* __restrict__ b2,
    const float* __restrict__ W3, const float* __restrict__ b3,
    float* __restrict__ out, int E, int n)
{
    extern __shared__ float sm[];
    float* W2s = sm;             // [j][i], stride 132: W2s[j*132+i] = W2[i][j]
    float* Zs = sm + 128 * 132;  // 128 j-rows x 32 edges of float2 (z,z)

    const int t = threadIdx.x, lane = t & 31, w = t >> 5;
    const int i0 = 4 * lane;

    for (int idx = t; idx < 128 * 128; idx += 128) {
        int j = idx & 127, i = idx >> 7;
        W2s[j * 132 + i] = W2[i * 128 + j];
    }
    const float4 b2v = *(const float4*)&b2[i0];
    const float4 w3v = *(const float4*)&W3[i0];
    const float b3v = b3[0];
    __syncthreads();

    const int ntiles = (E + 31) >> 5;
    for (int tile = blockIdx.x; tile < ntiles; tile += gridDim.x) {
        const int e0 = tile << 5;

        // ---- stage z1: thread (e = t&31, seg = t>>5) covers 32 j's of edge e
        {
            const int e = t & 31, seg = t >> 5;
            const int ge = e0 + e;
            float2* Z2 = (float2*)Zs;
            if (ge < E) {
                int s = src[ge];
                int d = dst[ge];
                // defensive clamp: turns a dtype surprise into rel_err, not a crash
                s = min(max(s, 0), n - 1);
                d = min(max(d, 0), n - 1);
                const float4* Pp = (const float4*)(g_P + (size_t)s * H + seg * 32);
                const float4* Qp = (const float4*)(g_Q + (size_t)d * H + seg * 32);
                #pragma unroll
                for (int u = 0; u < 8; ++u) {
                    float4 p = Pp[u], q = Qp[u];
                    int j = seg * 32 + u * 4;
                    float z0 = sigmoidf_(p.x + q.x);
                    float z1 = sigmoidf_(p.y + q.y);
                    float z2 = sigmoidf_(p.z + q.z);
                    float z3 = sigmoidf_(p.w + q.w);
                    Z2[(j + 0) * 32 + e] = make_float2(z0, z0);
                    Z2[(j + 1) * 32 + e] = make_float2(z1, z1);
                    Z2[(j + 2) * 32 + e] = make_float2(z2, z2);
                    Z2[(j + 3) * 32 + e] = make_float2(z3, z3);
                }
            } else {
                #pragma unroll
                for (int u = 0; u < 8; ++u) {
                    int j = seg * 32 + u * 4;
                    Z2[(j + 0) * 32 + e] = make_float2(0.f, 0.f);
                    Z2[(j + 1) * 32 + e] = make_float2(0.f, 0.f);
                    Z2[(j + 2) * 32 + e] = make_float2(0.f, 0.f);
                    Z2[(j + 3) * 32 + e] = make_float2(0.f, 0.f);
                }
            }
        }
        __syncthreads();

        // ---- layer-2 GEMM: acc[e] = pair-accumulators for outputs (i0..i0+3)
        ull acc[8][2];
        #pragma unroll
        for (int e = 0; e < 8; ++e) { acc[e][0] = 0ull; acc[e][1] = 0ull; }

        #pragma unroll 8
        for (int j = 0; j < 128; ++j) {
            ulonglong2 wv = *(const ulonglong2*)(W2s + j * 132 + i0);
            const ulonglong2* zp = (const ulonglong2*)(Zs + (j * 32 + 8 * w) * 2);
            ulonglong2 zA = zp[0], zB = zp[1], zC = zp[2], zD = zp[3];
            fma2(acc[0][0], wv.x, zA.x); fma2(acc[0][1], wv.y, zA.x);
            fma2(acc[1][0], wv.x, zA.y); fma2(acc[1][1], wv.y, zA.y);
            fma2(acc[2][0], wv.x, zB.x); fma2(acc[2][1], wv.y, zB.x);
            fma2(acc[3][0], wv.x, zB.y); fma2(acc[3][1], wv.y, zB.y);
            fma2(acc[4][0], wv.x, zC.x); fma2(acc[4][1], wv.y, zC.x);
            fma2(acc[5][0], wv.x, zC.y); fma2(acc[5][1], wv.y, zC.y);
            fma2(acc[6][0], wv.x, zD.x); fma2(acc[6][1], wv.y, zD.x);
            fma2(acc[7][0], wv.x, zD.y); fma2(acc[7][1], wv.y, zD.y);
        }

        // ---- epilogue: sigmoid, dot with W3, warp-reduce, write
        #pragma unroll
        for (int e = 0; e < 8; ++e) {
            float2 a01 = unpack2(acc[e][0]);
            float2 a23 = unpack2(acc[e][1]);
            float z0 = sigmoidf_(a01.x + b2v.x);
            float z1 = sigmoidf_(a01.y + b2v.y);
            float z2 = sigmoidf_(a23.x + b2v.z);
            float z3 = sigmoidf_(a23.y + b2v.w);
            float c = z0 * w3v.x + z1 * w3v.y + z2 * w3v.z + z3 * w3v.w;
            #pragma unroll
            for (int off = 16; off > 0; off >>= 1)
                c += __shfl_xor_sync(0xffffffffu, c, off);
            int ge = e0 + 8 * w + e;
            if (lane == 0 && ge < E) out[ge] = c + b3v;
        }
        __syncthreads();
    }
}

extern "C" void kernel_launch(void* const* d_in, const int* in_sizes, int n_in,
                              void* d_out, int out_size)
{
    const float* h1 = (const float*)d_in[0];
    const float* h2 = (const float*)d_in[1];
    const int* src = (const int*)d_in[2];   // int32: JAX default x64-disabled
    const int* dst = (const int*)d_in[3];
    const float* W1 = (const float*)d_in[4];
    const float* b1 = (const float*)d_in[5];
    const float* W2 = (const float*)d_in[6];
    const float* b2 = (const float*)d_in[7];
    const float* W3 = (const float*)d_in[8];
    const float* b3 = (const float*)d_in[9];
    float* out = (float*)d_out;

    const int n = in_sizes[0] / D;
    const int E = in_sizes[2];

    cudaFuncSetAttribute(precompute_kernel,
                         cudaFuncAttributeMaxDynamicSharedMemorySize, PRE_SMEM_BYTES);
    cudaFuncSetAttribute(edge_kernel,
                         cudaFuncAttributeMaxDynamicSharedMemorySize, EDGE_SMEM_BYTES);

    const int preBlocks = (n + 127) / 128;
    precompute_kernel<<<preBlocks, 128, PRE_SMEM_BYTES>>>(h1, h2, W1, b1, n);

    edge_kernel<<<296, 128, EDGE_SMEM_BYTES>>>(src, dst, W2, b2, W3, b3, out, E, n);
}

// round 5
// speedup vs baseline: 1.4457x; 1.4457x over previous
#include <cuda_runtime.h>
#include <cstdint>

#define D 64
#define H 128
#define NMAX 50048

__device__ __align__(16) float g_P[(size_t)NMAX * H];
__device__ __align__(16) float g_Q[(size_t)NMAX * H];

typedef unsigned long long ull;

__device__ __forceinline__ float sigmoidf_(float x) {
    return __fdividef(1.0f, 1.0f + __expf(-x));
}
__device__ __forceinline__ uint32_t cvt_bf16x2(float hi, float lo) {
    uint32_t r; asm("cvt.rn.bf16x2.f32 %0, %1, %2;" : "=r"(r) : "f"(hi), "f"(lo)); return r;
}
__device__ __forceinline__ float bf_lo(uint32_t u) { return __uint_as_float(u << 16); }
__device__ __forceinline__ float bf_hi(uint32_t u) { return __uint_as_float(u & 0xffff0000u); }

// m16n8k16 row.col bf16 MMA, fp32 accum (sm_80+ PTX — no arch-a features)
__device__ __forceinline__ void mma_bf16(float* c, uint4 a, uint2 b) {
    asm volatile(
        "mma.sync.aligned.m16n8k16.row.col.f32.bf16.bf16.f32 "
        "{%0,%1,%2,%3}, {%4,%5,%6,%7}, {%8,%9}, {%0,%1,%2,%3};"
        : "+f"(c[0]), "+f"(c[1]), "+f"(c[2]), "+f"(c[3])
        : "r"(a.x), "r"(a.y), "r"(a.z), "r"(a.w), "r"(b.x), "r"(b.y));
}

// ---------------------------------------------------------------------------
// Kernel 1: per-node precompute (unchanged — known good, ~106us)
// ---------------------------------------------------------------------------
__device__ __forceinline__ void fma2(ull& acc, ull a, ull b) {
    asm("fma.rn.f32x2 %0, %1, %2, %0;" : "+l"(acc) : "l"(a), "l"(b));
}
__device__ __forceinline__ ull pack2(float x, float y) {
    ull r; asm("mov.b64 %0, {%1, %2};" : "=l"(r) : "f"(x), "f"(y)); return r;
}
__device__ __forceinline__ float2 unpack2(ull v) {
    float2 r; asm("mov.b64 {%0, %1}, %2;" : "=f"(r.x), "=f"(r.y) : "l"(v)); return r;
}

#define PRE_SMEM_FLOATS (3 * 64 * 129 + 2 * 512)
#define PRE_SMEM_BYTES (PRE_SMEM_FLOATS * 4)

__global__ void __launch_bounds__(128) precompute_kernel(
    const float* __restrict__ h1, const float* __restrict__ h2,
    const float* __restrict__ W1, const float* __restrict__ b1, int n)
{
    extern __shared__ float sm[];
    float* WaT = sm;
    float* WbT = sm + 64 * 129;
    float* WcT = sm + 2 * 64 * 129;
    float* hs1 = sm + 3 * 64 * 129;
    float* hs2 = hs1 + 512;
    const int t = threadIdx.x;

    for (int idx = t; idx < 64 * 128; idx += 128) {
        int k = idx & 63, i = idx >> 6;
        WaT[k * 129 + i] = W1[i * 256 + k];
        WbT[k * 129 + i] = W1[i * 256 + 64 + k];
        WcT[k * 129 + i] = W1[i * 256 + 128 + k] + W1[i * 256 + 192 + k];
    }
    const float b1i = b1[t];
    __syncthreads();

    const int n0b = blockIdx.x * 128;
    for (int g = 0; g < 16; ++g) {
        const int n0 = n0b + g * 8;
        #pragma unroll
        for (int r = 0; r < 4; ++r) {
            int idx = r * 128 + t;
            int k = idx & 63, nn = idx >> 6;
            int node = n0 + nn;
            float v1 = 0.f, v2 = 0.f;
            if (node < n) { v1 = h1[node * D + k]; v2 = h2[node * D + k]; }
            hs1[k * 8 + nn] = v1;
            hs2[k * 8 + nn] = v2;
        }
        __syncthreads();

        ull accP[4] = {0, 0, 0, 0}, accQ[4] = {0, 0, 0, 0};
        #pragma unroll 8
        for (int k = 0; k < 64; ++k) {
            float wa = WaT[k * 129 + t];
            float wb = WbT[k * 129 + t];
            float wc = WcT[k * 129 + t];
            ull wa2 = pack2(wa, wa), wb2 = pack2(wb, wb), wc2 = pack2(wc, wc);
            const ulonglong2* p1 = (const ulonglong2*)(hs1 + k * 8);
            const ulonglong2* p2 = (const ulonglong2*)(hs2 + k * 8);
            ulonglong2 x1a = p1[0], x1b = p1[1];
            ulonglong2 x2a = p2[0], x2b = p2[1];
            fma2(accP[0], wa2, x1a.x); fma2(accP[1], wa2, x1a.y);
            fma2(accP[2], wa2, x1b.x); fma2(accP[3], wa2, x1b.y);
            fma2(accP[0], wc2, x2a.x); fma2(accP[1], wc2, x2a.y);
            fma2(accP[2], wc2, x2b.x); fma2(accP[3], wc2, x2b.y);
            fma2(accQ[0], wb2, x1a.x); fma2(accQ[1], wb2, x1a.y);
            fma2(accQ[2], wb2, x1b.x); fma2(accQ[3], wb2, x1b.y);
        }
        #pragma unroll
        for (int p = 0; p < 4; ++p) {
            float2 vp = unpack2(accP[p]);
            float2 vq = unpack2(accQ[p]);
            int na = n0 + 2 * p, nb = na + 1;
            if (na < n) { g_P[(size_t)na * H + t] = vp.x + b1i; g_Q[(size_t)na * H + t] = vq.x; }
            if (nb < n) { g_P[(size_t)nb * H + t] = vp.y + b1i; g_Q[(size_t)nb * H + t] = vq.y; }
        }
        __syncthreads();
    }
}

// ---------------------------------------------------------------------------
// Kernel 2: per-edge, mma.sync bf16x3 (HMMA tensor pipe)
// Tile = 64 edges, block = 128 threads (4 warps). Warp w: rows 32w..32w+31,
// all 64 edges. A (W2 hi/lo) resident in smem in m16n8k16 fragment layout;
// B (z1 hi/lo) staged per tile in fragment layout with nt-XOR bank swizzle.
// ---------------------------------------------------------------------------
#define TILE_E 64
#define SM_AHI 0
#define SM_ALO 32768
#define SM_BHI 65536
#define SM_BLO 81920
#define SM_PART 98304          // 4*64 floats
#define SM_B2   (SM_PART + 1024)
#define SM_W3   (SM_B2 + 512)
#define EDGE_SMEM_BYTES (SM_W3 + 512)

__global__ void __launch_bounds__(128) edge_kernel(
    const int* __restrict__ src, const int* __restrict__ dst,
    const float* __restrict__ W2, const float* __restrict__ b2,
    const float* __restrict__ W3, const float* __restrict__ b3,
    float* __restrict__ out, int E, int n)
{
    extern __shared__ char smc[];
    uint4* Ahi = (uint4*)(smc + SM_AHI);     // [mt][kt][lane] -> uint4
    uint4* Alo = (uint4*)(smc + SM_ALO);
    uint32_t* Bhi = (uint32_t*)(smc + SM_BHI); // [nt][kt][lane] -> 2 x u32
    uint32_t* Blo = (uint32_t*)(smc + SM_BLO);
    float* part = (float*)(smc + SM_PART);     // [4][64]
    float* b2s = (float*)(smc + SM_B2);
    float* w3s = (float*)(smc + SM_W3);

    const int t = threadIdx.x, lane = t & 31, w = t >> 5;
    const int gid = lane >> 2, tig = lane & 3;

    b2s[t] = b2[t];
    w3s[t] = W3[t];

    // ---- Build W2 hi/lo fragments (once). Scratch = B region (16KB per chunk).
    float* scratch = (float*)(smc + SM_BHI);   // 32 rows x 128 fp32
    for (int chunk = 0; chunk < 4; ++chunk) {
        const int R0 = 32 * chunk;
        __syncthreads();
        #pragma unroll
        for (int i = 0; i < 8; ++i) {
            int fidx = i * 128 + t;            // float4 index in 32x128 slab
            ((float4*)scratch)[fidx] = ((const float4*)W2)[R0 * 32 + fidx];
        }
        __syncthreads();
        #pragma unroll
        for (int i = 0; i < 4; ++i) {
            int fid = i * 128 + t;             // 512 frags per chunk
            int fl = fid & 31, kt = (fid >> 5) & 7, mtl = fid >> 8;  // 0..1
            int mt = 2 * chunk + mtl;
            int fg = fl >> 2, ft = fl & 3;
            int lr0 = mtl * 16 + fg, lr1 = lr0 + 8;
            int k0 = kt * 16 + ft * 2;
            float w00 = scratch[lr0 * 128 + k0],     w01 = scratch[lr0 * 128 + k0 + 1];
            float w10 = scratch[lr1 * 128 + k0],     w11 = scratch[lr1 * 128 + k0 + 1];
            float w02 = scratch[lr0 * 128 + k0 + 8], w03 = scratch[lr0 * 128 + k0 + 9];
            float w12 = scratch[lr1 * 128 + k0 + 8], w13 = scratch[lr1 * 128 + k0 + 9];
            uint4 hi, lo;
            hi.x = cvt_bf16x2(w01, w00);
            lo.x = cvt_bf16x2(w01 - bf_hi(hi.x), w00 - bf_lo(hi.x));
            hi.y = cvt_bf16x2(w11, w10);
            lo.y = cvt_bf16x2(w11 - bf_hi(hi.y), w10 - bf_lo(hi.y));
            hi.z = cvt_bf16x2(w03, w02);
            lo.z = cvt_bf16x2(w03 - bf_hi(hi.z), w02 - bf_lo(hi.z));
            hi.w = cvt_bf16x2(w13, w12);
            lo.w = cvt_bf16x2(w13 - bf_hi(hi.w), w12 - bf_lo(hi.w));
            int idx = (mt * 8 + kt) * 32 + fl;
            Ahi[idx] = hi;
            Alo[idx] = lo;
        }
    }
    __syncthreads();

    // per-lane epilogue constants (rows 32w+gid + {0,8,16,24})
    const int r0 = 32 * w + gid;
    const float b2a = b2s[r0], b2b = b2s[r0 + 8], b2c = b2s[r0 + 16], b2d = b2s[r0 + 24];
    const float w3a = w3s[r0], w3b = w3s[r0 + 8], w3c = w3s[r0 + 16], w3d = w3s[r0 + 24];
    const float b3v = b3[0];

    const int ntiles = (E + TILE_E - 1) / TILE_E;
    for (int tile = blockIdx.x; tile < ntiles; tile += gridDim.x) {
        const int e0 = tile * TILE_E;

        // ---- stage z1 hi/lo into B fragment layout
        {
            const int e = t & 63, kh = t >> 6;   // edge, k-half (0:k<64, 1:k>=64)
            const int ge = e0 + e;
            const int nt = e >> 3;
            const int laneb = (e & 7) * 4;
            const int lx = nt << 2;              // storage XOR swizzle
            if (ge < E) {
                int s = src[ge], d = dst[ge];
                s = min(max(s, 0), n - 1);
                d = min(max(d, 0), n - 1);
                const float4* Pp = (const float4*)(g_P + (size_t)s * H + kh * 64);
                const float4* Qp = (const float4*)(g_Q + (size_t)d * H + kh * 64);
                #pragma unroll
                for (int u = 0; u < 16; ++u) {
                    float4 p = Pp[u], q = Qp[u];
                    float z0 = sigmoidf_(p.x + q.x);
                    float z1 = sigmoidf_(p.y + q.y);
                    float z2 = sigmoidf_(p.z + q.z);
                    float z3 = sigmoidf_(p.w + q.w);
                    uint32_t h01 = cvt_bf16x2(z1, z0);
                    uint32_t l01 = cvt_bf16x2(z1 - bf_hi(h01), z0 - bf_lo(h01));
                    uint32_t h23 = cvt_bf16x2(z3, z2);
                    uint32_t l23 = cvt_bf16x2(z3 - bf_hi(h23), z2 - bf_lo(h23));
                    int k = kh * 64 + u * 4;
                    int kt = k >> 4, reg = (k >> 3) & 1;
                    int l0 = (laneb + ((k & 7) >> 1)) ^ lx;
                    int l1 = (laneb + (((k + 2) & 7) >> 1)) ^ lx;
                    int base = (nt * 8 + kt) * 64;
                    Bhi[base + l0 * 2 + reg] = h01;
                    Bhi[base + l1 * 2 + reg] = h23;
                    Blo[base + l0 * 2 + reg] = l01;
                    Blo[base + l1 * 2 + reg] = l23;
                }
            } else {
                #pragma unroll
                for (int u = 0; u < 16; ++u) {
                    int k = kh * 64 + u * 4;
                    int kt = k >> 4, reg = (k >> 3) & 1;
                    int l0 = (laneb + ((k & 7) >> 1)) ^ lx;
                    int l1 = (laneb + (((k + 2) & 7) >> 1)) ^ lx;
                    int base = (nt * 8 + kt) * 64;
                    Bhi[base + l0 * 2 + reg] = 0; Bhi[base + l1 * 2 + reg] = 0;
                    Blo[base + l0 * 2 + reg] = 0; Blo[base + l1 * 2 + reg] = 0;
                }
            }
        }
        __syncthreads();

        // ---- MMA mainloop: acc[m][nt][4], bf16x3
        float acc[2][8][4];
        #pragma unroll
        for (int m = 0; m < 2; ++m)
            #pragma unroll
            for (int nt = 0; nt < 8; ++nt)
                #pragma unroll
                for (int r = 0; r < 4; ++r) acc[m][nt][r] = 0.f;

        #pragma unroll 1
        for (int kt = 0; kt < 8; ++kt) {
            uint4 ah0 = Ahi[((2 * w) * 8 + kt) * 32 + lane];
            uint4 ah1 = Ahi[((2 * w + 1) * 8 + kt) * 32 + lane];
            uint4 al0 = Alo[((2 * w) * 8 + kt) * 32 + lane];
            uint4 al1 = Alo[((2 * w + 1) * 8 + kt) * 32 + lane];
            #pragma unroll
            for (int nt = 0; nt < 8; ++nt) {
                int bl = lane ^ (nt << 2);
                uint2 bh = ((const uint2*)Bhi)[(nt * 8 + kt) * 32 + bl];
                uint2 bl2 = ((const uint2*)Blo)[(nt * 8 + kt) * 32 + bl];
                mma_bf16(acc[0][nt], ah0, bh);
                mma_bf16(acc[0][nt], ah0, bl2);
                mma_bf16(acc[0][nt], al0, bh);
                mma_bf16(acc[1][nt], ah1, bh);
                mma_bf16(acc[1][nt], ah1, bl2);
                mma_bf16(acc[1][nt], al1, bh);
            }
        }

        // ---- epilogue: sigmoid + W3 dot + reduce over gid lanes
        #pragma unroll
        for (int nt = 0; nt < 8; ++nt) {
            float s0 = sigmoidf_(acc[0][nt][0] + b2a) * w3a
                     + sigmoidf_(acc[0][nt][2] + b2b) * w3b
                     + sigmoidf_(acc[1][nt][0] + b2c) * w3c
                     + sigmoidf_(acc[1][nt][2] + b2d) * w3d;
            float s1 = sigmoidf_(acc[0][nt][1] + b2a) * w3a
                     + sigmoidf_(acc[0][nt][3] + b2b) * w3b
                     + sigmoidf_(acc[1][nt][1] + b2c) * w3c
                     + sigmoidf_(acc[1][nt][3] + b2d) * w3d;
            s0 += __shfl_xor_sync(0xffffffffu, s0, 4);
            s0 += __shfl_xor_sync(0xffffffffu, s0, 8);
            s0 += __shfl_xor_sync(0xffffffffu, s0, 16);
            s1 += __shfl_xor_sync(0xffffffffu, s1, 4);
            s1 += __shfl_xor_sync(0xffffffffu, s1, 8);
            s1 += __shfl_xor_sync(0xffffffffu, s1, 16);
            if (gid == 0) {
                part[w * 64 + nt * 8 + tig * 2] = s0;
                part[w * 64 + nt * 8 + tig * 2 + 1] = s1;
            }
        }
        __syncthreads();

        if (t < 64) {
            int ge = e0 + t;
            if (ge < E)
                out[ge] = part[t] + part[64 + t] + part[128 + t] + part[192 + t] + b3v;
        }
        __syncthreads();
    }
}

extern "C" void kernel_launch(void* const* d_in, const int* in_sizes, int n_in,
                              void* d_out, int out_size)
{
    const float* h1 = (const float*)d_in[0];
    const float* h2 = (const float*)d_in[1];
    const int* src = (const int*)d_in[2];
    const int* dst = (const int*)d_in[3];
    const float* W1 = (const float*)d_in[4];
    const float* b1 = (const float*)d_in[5];
    const float* W2 = (const float*)d_in[6];
    const float* b2 = (const float*)d_in[7];
    const float* W3 = (const float*)d_in[8];
    const float* b3 = (const float*)d_in[9];
    float* out = (float*)d_out;

    const int n = in_sizes[0] / D;
    const int E = in_sizes[2];

    cudaFuncSetAttribute(precompute_kernel,
                         cudaFuncAttributeMaxDynamicSharedMemorySize, PRE_SMEM_BYTES);
    cudaFuncSetAttribute(edge_kernel,
                         cudaFuncAttributeMaxDynamicSharedMemorySize, EDGE_SMEM_BYTES);

    const int preBlocks = (n + 127) / 128;
    precompute_kernel<<<preBlocks, 128, PRE_SMEM_BYTES>>>(h1, h2, W1, b1, n);

    edge_kernel<<<296, 128, EDGE_SMEM_BYTES>>>(src, dst, W2, b2, W3, b3, out, E, n);
}

// round 6
// speedup vs baseline: 3.1811x; 2.2004x over previous
#include <cuda_runtime.h>
#include <cstdint>

#define D 64
#define H 128
#define NMAX 50048

__device__ __align__(16) float g_P[(size_t)NMAX * H];
__device__ __align__(16) float g_Q[(size_t)NMAX * H];
__device__ int g_ctr_pre;
__device__ int g_ctr_edge;

typedef unsigned long long ull;

__device__ __forceinline__ float sigt(float x) {
    float t;
    asm("tanh.approx.f32 %0, %1;" : "=f"(t) : "f"(x * 0.5f));
    return fmaf(t, 0.5f, 0.5f);
}
__device__ __forceinline__ uint32_t cvt_bf16x2(float hi, float lo) {
    uint32_t r; asm("cvt.rn.bf16x2.f32 %0, %1, %2;" : "=r"(r) : "f"(hi), "f"(lo)); return r;
}
__device__ __forceinline__ float bf_lo(uint32_t u) { return __uint_as_float(u << 16); }
__device__ __forceinline__ float bf_hi(uint32_t u) { return __uint_as_float(u & 0xffff0000u); }

__device__ __forceinline__ void mma_bf16(float* c, uint4 a, uint2 b) {
    asm volatile(
        "mma.sync.aligned.m16n8k16.row.col.f32.bf16.bf16.f32 "
        "{%0,%1,%2,%3}, {%4,%5,%6,%7}, {%8,%9}, {%0,%1,%2,%3};"
        : "+f"(c[0]), "+f"(c[1]), "+f"(c[2]), "+f"(c[3])
        : "r"(a.x), "r"(a.y), "r"(a.z), "r"(a.w), "r"(b.x), "r"(b.y));
}

// Build hi/lo bf16 A-fragments (m16n8k16 row-major layout, empirically validated
// in R5) from a 32-row fp32 scratch slab with ncols = nkt*16.
__device__ __forceinline__ void build_frags(const float* scr, uint4* hiA, uint4* loA,
                                            int mt_base, int nkt, int t, int nth)
{
    const int ncols = nkt * 16;
    for (int fid = t; fid < 64 * nkt; fid += nth) {
        int fl = fid & 31;
        int kt = (fid >> 5) % nkt;
        int mtl = fid / (32 * nkt);
        int fg = fl >> 2, ft = fl & 3;
        int lr0 = mtl * 16 + fg, lr1 = lr0 + 8;
        int k0 = kt * 16 + ft * 2;
        float w00 = scr[lr0 * ncols + k0],     w01 = scr[lr0 * ncols + k0 + 1];
        float w10 = scr[lr1 * ncols + k0],     w11 = scr[lr1 * ncols + k0 + 1];
        float w02 = scr[lr0 * ncols + k0 + 8], w03 = scr[lr0 * ncols + k0 + 9];
        float w12 = scr[lr1 * ncols + k0 + 8], w13 = scr[lr1 * ncols + k0 + 9];
        uint4 hi, lo;
        hi.x = cvt_bf16x2(w01, w00); lo.x = cvt_bf16x2(w01 - bf_hi(hi.x), w00 - bf_lo(hi.x));
        hi.y = cvt_bf16x2(w11, w10); lo.y = cvt_bf16x2(w11 - bf_hi(hi.y), w10 - bf_lo(hi.y));
        hi.z = cvt_bf16x2(w03, w02); lo.z = cvt_bf16x2(w03 - bf_hi(hi.z), w02 - bf_lo(hi.z));
        hi.w = cvt_bf16x2(w13, w12); lo.w = cvt_bf16x2(w13 - bf_hi(hi.w), w12 - bf_lo(hi.w));
        int idx = ((mt_base + mtl) * nkt + kt) * 32 + fl;
        hiA[idx] = hi;
        loA[idx] = lo;
    }
}

// Stage 4 consecutive-k values (k%4==0) for fragment-column n of group nt into
// hi/lo B buffers. Writer XOR = e>>2 (= 2*nt + n>>2); reader applies the same.
__device__ __forceinline__ void stage4(uint32_t* hiB, uint32_t* loB,
                                       int nt, int n, int xe, int k,
                                       float z0, float z1, float z2, float z3)
{
    uint32_t h01 = cvt_bf16x2(z1, z0);
    uint32_t l01 = cvt_bf16x2(z1 - bf_hi(h01), z0 - bf_lo(h01));
    uint32_t h23 = cvt_bf16x2(z3, z2);
    uint32_t l23 = cvt_bf16x2(z3 - bf_hi(h23), z2 - bf_lo(h23));
    int kt = k >> 4, kq = (k & 7) >> 1, reg = (k >> 3) & 1;
    int l0 = (n * 4 + kq) ^ xe, l1 = (n * 4 + kq + 1) ^ xe;
    int base = (nt * 8 + kt) * 64;
    hiB[base + l0 * 2 + reg] = h01;
    hiB[base + l1 * 2 + reg] = h23;
    loB[base + l0 * 2 + reg] = l01;
    loB[base + l1 * 2 + reg] = l23;
}

__global__ void init_ctrs() { g_ctr_pre = 0; g_ctr_edge = 0; }

// ---------------------------------------------------------------------------
// Precompute: P[n] = b1 + [Wa | Wc+Wd] @ [h1;h2],  Q[n] = Wb @ h1
// 256 threads, 8 independent warps, 32 nodes per warp-tile, bf16x3 HMMA.
// ---------------------------------------------------------------------------
#define P_A1HI 0
#define P_A1LO 32768
#define P_A2HI 65536
#define P_A2LO 81920
#define P_B    98304            // 8 warps x 16KB (hi 8KB + lo 8KB)
#define P_B1S  229376
#define PRE_SMEM_BYTES 229888

__global__ void __launch_bounds__(256) precompute_kernel(
    const float* __restrict__ h1, const float* __restrict__ h2,
    const float* __restrict__ W1, const float* __restrict__ b1, int n)
{
    extern __shared__ char smc[];
    uint4* A1hi = (uint4*)(smc + P_A1HI);
    uint4* A1lo = (uint4*)(smc + P_A1LO);
    uint4* A2hi = (uint4*)(smc + P_A2HI);
    uint4* A2lo = (uint4*)(smc + P_A2LO);
    float* b1s = (float*)(smc + P_B1S);

    const int t = threadIdx.x, lane = t & 31, w = t >> 5;
    const int gid = lane >> 2, tig = lane & 3;

    // Build A1 = [Wa | Wc+Wd] (128x128) and A2 = Wb (128x64) fragments.
    {
        float* scr = (float*)(smc + P_B);   // 16KB scratch (reuses B region)
        for (int chunk = 0; chunk < 4; ++chunk) {
            const int R0 = chunk * 32;
            __syncthreads();
            for (int idx = t; idx < 4096; idx += 256) {
                int r = idx >> 7, k = idx & 127;
                float v;
                if (k < 64) v = W1[(R0 + r) * 256 + k];
                else        v = W1[(R0 + r) * 256 + 64 + k] + W1[(R0 + r) * 256 + 128 + k];
                scr[r * 128 + k] = v;
            }
            __syncthreads();
            build_frags(scr, A1hi, A1lo, chunk * 2, 8, t, 256);
        }
        for (int chunk = 0; chunk < 4; ++chunk) {
            const int R0 = chunk * 32;
            __syncthreads();
            for (int idx = t; idx < 2048; idx += 256) {
                int r = idx >> 6, k = idx & 63;
                scr[r * 64 + k] = W1[(R0 + r) * 256 + 64 + k];
            }
            __syncthreads();
            build_frags(scr, A2hi, A2lo, chunk * 2, 4, t, 256);
        }
    }
    if (t < 128) b1s[t] = b1[t];
    __syncthreads();

    float b1r0[8], b1r1[8];
    #pragma unroll
    for (int mt = 0; mt < 8; ++mt) {
        b1r0[mt] = b1s[mt * 16 + gid];
        b1r1[mt] = b1s[mt * 16 + gid + 8];
    }

    uint32_t* hiB = (uint32_t*)(smc + P_B + w * 16384);
    uint32_t* loB = hiB + 2048;
    const int e = lane, nt_e = e >> 3, n_e = e & 7, xe = e >> 2;
    const int lq = lane >> 4;
    const int ntiles = (n + 31) >> 5;

    for (;;) {
        int tile;
        if (lane == 0) tile = atomicAdd(&g_ctr_pre, 1);
        tile = __shfl_sync(0xffffffffu, tile, 0);
        if (tile >= ntiles) break;
        const int nb = tile * 32;
        const int node = nb + e;
        __syncwarp();

        // stage B = [h1(64); h2(64)] hi/lo for this lane's node
        if (node < n) {
            const float4* H1 = (const float4*)(h1 + (size_t)node * D);
            const float4* H2 = (const float4*)(h2 + (size_t)node * D);
            #pragma unroll 8
            for (int u = 0; u < 16; ++u) {
                float4 v = H1[u];
                stage4(hiB, loB, nt_e, n_e, xe, u * 4, v.x, v.y, v.z, v.w);
            }
            #pragma unroll 8
            for (int u = 0; u < 16; ++u) {
                float4 v = H2[u];
                stage4(hiB, loB, nt_e, n_e, xe, 64 + u * 4, v.x, v.y, v.z, v.w);
            }
        } else {
            #pragma unroll 8
            for (int u = 0; u < 32; ++u)
                stage4(hiB, loB, nt_e, n_e, xe, u * 4, 0.f, 0.f, 0.f, 0.f);
        }
        __syncwarp();

        float acc[8][4][4];

        // ---- P pass: A1, K=128
        #pragma unroll
        for (int mt = 0; mt < 8; ++mt)
            #pragma unroll
            for (int nt = 0; nt < 4; ++nt)
                #pragma unroll
                for (int r = 0; r < 4; ++r) acc[mt][nt][r] = 0.f;

        #pragma unroll 1
        for (int kt = 0; kt < 8; ++kt) {
            uint2 bh[4], bo[4];
            #pragma unroll
            for (int nt = 0; nt < 4; ++nt) {
                int lp = lane ^ (2 * nt + lq);
                bh[nt] = ((const uint2*)hiB)[(nt * 8 + kt) * 32 + lp];
                bo[nt] = ((const uint2*)loB)[(nt * 8 + kt) * 32 + lp];
            }
            #pragma unroll
            for (int mt = 0; mt < 8; ++mt) {
                uint4 ah = A1hi[(mt * 8 + kt) * 32 + lane];
                uint4 al = A1lo[(mt * 8 + kt) * 32 + lane];
                #pragma unroll
                for (int nt = 0; nt < 4; ++nt) {
                    mma_bf16(acc[mt][nt], ah, bh[nt]);
                    mma_bf16(acc[mt][nt], ah, bo[nt]);
                    mma_bf16(acc[mt][nt], al, bh[nt]);
                }
            }
        }
        #pragma unroll
        for (int nt = 0; nt < 4; ++nt) {
            int n0 = nb + nt * 8 + tig * 2, n1 = n0 + 1;
            #pragma unroll
            for (int mt = 0; mt < 8; ++mt) {
                int r0 = mt * 16 + gid, r1 = r0 + 8;
                if (n0 < n) {
                    g_P[(size_t)n0 * H + r0] = acc[mt][nt][0] + b1r0[mt];
                    g_P[(size_t)n0 * H + r1] = acc[mt][nt][2] + b1r1[mt];
                }
                if (n1 < n) {
                    g_P[(size_t)n1 * H + r0] = acc[mt][nt][1] + b1r0[mt];
                    g_P[(size_t)n1 * H + r1] = acc[mt][nt][3] + b1r1[mt];
                }
            }
        }

        // ---- Q pass: A2, K=64 (B slabs kt 0..3 hold h1)
        #pragma unroll
        for (int mt = 0; mt < 8; ++mt)
            #pragma unroll
            for (int nt = 0; nt < 4; ++nt)
                #pragma unroll
                for (int r = 0; r < 4; ++r) acc[mt][nt][r] = 0.f;

        #pragma unroll 1
        for (int kt = 0; kt < 4; ++kt) {
            uint2 bh[4], bo[4];
            #pragma unroll
            for (int nt = 0; nt < 4; ++nt) {
                int lp = lane ^ (2 * nt + lq);
                bh[nt] = ((const uint2*)hiB)[(nt * 8 + kt) * 32 + lp];
                bo[nt] = ((const uint2*)loB)[(nt * 8 + kt) * 32 + lp];
            }
            #pragma unroll
            for (int mt = 0; mt < 8; ++mt) {
                uint4 ah = A2hi[(mt * 4 + kt) * 32 + lane];
                uint4 al = A2lo[(mt * 4 + kt) * 32 + lane];
                #pragma unroll
                for (int nt = 0; nt < 4; ++nt) {
                    mma_bf16(acc[mt][nt], ah, bh[nt]);
                    mma_bf16(acc[mt][nt], ah, bo[nt]);
                    mma_bf16(acc[mt][nt], al, bh[nt]);
                }
            }
        }
        #pragma unroll
        for (int nt = 0; nt < 4; ++nt) {
            int n0 = nb + nt * 8 + tig * 2, n1 = n0 + 1;
            #pragma unroll
            for (int mt = 0; mt < 8; ++mt) {
                int r0 = mt * 16 + gid, r1 = r0 + 8;
                if (n0 < n) {
                    g_Q[(size_t)n0 * H + r0] = acc[mt][nt][0];
                    g_Q[(size_t)n0 * H + r1] = acc[mt][nt][2];
                }
                if (n1 < n) {
                    g_Q[(size_t)n1 * H + r0] = acc[mt][nt][1];
                    g_Q[(size_t)n1 * H + r1] = acc[mt][nt][3];
                }
            }
        }
    }
}

// ---------------------------------------------------------------------------
// Edge kernel: warp-independent, 32 edges per warp-tile, bf16x3 HMMA.
// ---------------------------------------------------------------------------
#define E_AHI 0
#define E_ALO 32768
#define E_B   65536             // 8 warps x 16KB
#define E_B2S 196608
#define E_W3S 197120
#define EDGE_SMEM_BYTES 197632

__global__ void __launch_bounds__(256) edge_kernel(
    const int* __restrict__ src, const int* __restrict__ dst,
    const float* __restrict__ W2, const float* __restrict__ b2,
    const float* __restrict__ W3, const float* __restrict__ b3,
    float* __restrict__ out, int E, int n)
{
    extern __shared__ char smc[];
    uint4* Ahi = (uint4*)(smc + E_AHI);
    uint4* Alo = (uint4*)(smc + E_ALO);
    float* b2s = (float*)(smc + E_B2S);
    float* w3s = (float*)(smc + E_W3S);

    const int t = threadIdx.x, lane = t & 31, w = t >> 5;
    const int gid = lane >> 2, tig = lane & 3;

    // Build W2 fragments (hi/lo) once.
    {
        float* scr = (float*)(smc + E_B);
        for (int chunk = 0; chunk < 4; ++chunk) {
            __syncthreads();
            for (int i = t; i < 1024; i += 256)
                ((float4*)scr)[i] = ((const float4*)W2)[chunk * 1024 + i];
            __syncthreads();
            build_frags(scr, Ahi, Alo, chunk * 2, 8, t, 256);
        }
    }
    if (t < 128) { b2s[t] = b2[t]; w3s[t] = W3[t]; }
    __syncthreads();

    float b2r0[8], b2r1[8], w3r0[8], w3r1[8];
    #pragma unroll
    for (int mt = 0; mt < 8; ++mt) {
        b2r0[mt] = b2s[mt * 16 + gid];
        b2r1[mt] = b2s[mt * 16 + gid + 8];
        w3r0[mt] = w3s[mt * 16 + gid];
        w3r1[mt] = w3s[mt * 16 + gid + 8];
    }
    const float b3v = b3[0];

    uint32_t* hiB = (uint32_t*)(smc + E_B + w * 16384);
    uint32_t* loB = hiB + 2048;
    const int e = lane, nt_e = e >> 3, n_e = e & 7, xe = e >> 2;
    const int lq = lane >> 4;
    const int ntiles = (E + 31) >> 5;

    for (;;) {
        int tile;
        if (lane == 0) tile = atomicAdd(&g_ctr_edge, 1);
        tile = __shfl_sync(0xffffffffu, tile, 0);
        if (tile >= ntiles) break;
        const int e0 = tile * 32;
        const int ge = e0 + e;
        __syncwarp();

        // stage z1 = sigmoid(P[src] + Q[dst]) hi/lo for this lane's edge
        if (ge < E) {
            int s = min(max(src[ge], 0), n - 1);
            int d = min(max(dst[ge], 0), n - 1);
            const float4* Pp = (const float4*)(g_P + (size_t)s * H);
            const float4* Qp = (const float4*)(g_Q + (size_t)d * H);
            #pragma unroll 8
            for (int u = 0; u < 32; ++u) {
                float4 p = Pp[u], q = Qp[u];
                stage4(hiB, loB, nt_e, n_e, xe, u * 4,
                       sigt(p.x + q.x), sigt(p.y + q.y),
                       sigt(p.z + q.z), sigt(p.w + q.w));
            }
        } else {
            #pragma unroll 8
            for (int u = 0; u < 32; ++u)
                stage4(hiB, loB, nt_e, n_e, xe, u * 4, 0.f, 0.f, 0.f, 0.f);
        }
        __syncwarp();

        float acc[8][4][4];
        #pragma unroll
        for (int mt = 0; mt < 8; ++mt)
            #pragma unroll
            for (int nt = 0; nt < 4; ++nt)
                #pragma unroll
                for (int r = 0; r < 4; ++r) acc[mt][nt][r] = 0.f;

        #pragma unroll 1
        for (int kt = 0; kt < 8; ++kt) {
            uint2 bh[4], bo[4];
            #pragma unroll
            for (int nt = 0; nt < 4; ++nt) {
                int lp = lane ^ (2 * nt + lq);
                bh[nt] = ((const uint2*)hiB)[(nt * 8 + kt) * 32 + lp];
                bo[nt] = ((const uint2*)loB)[(nt * 8 + kt) * 32 + lp];
            }
            #pragma unroll
            for (int mt = 0; mt < 8; ++mt) {
                uint4 ah = Ahi[(mt * 8 + kt) * 32 + lane];
                uint4 al = Alo[(mt * 8 + kt) * 32 + lane];
                #pragma unroll
                for (int nt = 0; nt < 4; ++nt) {
                    mma_bf16(acc[mt][nt], ah, bh[nt]);
                    mma_bf16(acc[mt][nt], ah, bo[nt]);
                    mma_bf16(acc[mt][nt], al, bh[nt]);
                }
            }
        }

        // epilogue: sigmoid + W3 dot, reduce over gid (lane bits 2..4)
        #pragma unroll
        for (int nt = 0; nt < 4; ++nt) {
            float s0 = 0.f, s1 = 0.f;
            #pragma unroll
            for (int mt = 0; mt < 8; ++mt) {
                s0 += sigt(acc[mt][nt][0] + b2r0[mt]) * w3r0[mt]
                    + sigt(acc[mt][nt][2] + b2r1[mt]) * w3r1[mt];
                s1 += sigt(acc[mt][nt][1] + b2r0[mt]) * w3r0[mt]
                    + sigt(acc[mt][nt][3] + b2r1[mt]) * w3r1[mt];
            }
            #pragma unroll
            for (int off = 4; off <= 16; off <<= 1) {
                s0 += __shfl_xor_sync(0xffffffffu, s0, off);
                s1 += __shfl_xor_sync(0xffffffffu, s1, off);
            }
            if (gid == 0) {
                int go = e0 + nt * 8 + tig * 2;
                if (go + 1 < E)
                    *(float2*)(out + go) = make_float2(s0 + b3v, s1 + b3v);
                else if (go < E)
                    out[go] = s0 + b3v;
            }
        }
    }
}

extern "C" void kernel_launch(void* const* d_in, const int* in_sizes, int n_in,
                              void* d_out, int out_size)
{
    const float* h1 = (const float*)d_in[0];
    const float* h2 = (const float*)d_in[1];
    const int* src = (const int*)d_in[2];
    const int* dst = (const int*)d_in[3];
    const float* W1 = (const float*)d_in[4];
    const float* b1 = (const float*)d_in[5];
    const float* W2 = (const float*)d_in[6];
    const float* b2 = (const float*)d_in[7];
    const float* W3 = (const float*)d_in[8];
    const float* b3 = (const float*)d_in[9];
    float* out = (float*)d_out;

    const int n = in_sizes[0] / D;
    const int E = in_sizes[2];

    cudaFuncSetAttribute(precompute_kernel,
                         cudaFuncAttributeMaxDynamicSharedMemorySize, PRE_SMEM_BYTES);
    cudaFuncSetAttribute(edge_kernel,
                         cudaFuncAttributeMaxDynamicSharedMemorySize, EDGE_SMEM_BYTES);

    init_ctrs<<<1, 1>>>();
    precompute_kernel<<<148, 256, PRE_SMEM_BYTES>>>(h1, h2, W1, b1, n);
    edge_kernel<<<148, 256, EDGE_SMEM_BYTES>>>(src, dst, W2, b2, W3, b3, out, E, n);
}